// round 1
// baseline (speedup 1.0000x reference)
#include <cuda_runtime.h>
#include <math.h>

#define N_ROWS 65536
#define K_CL   1024
#define D_DIM  256
#define A_DIM  64

#define BM 64   // rows per block
#define BK 64   // clusters per k-tile
#define BD 16   // d-slice

// scratch (device globals: allocation-free per harness rules)
__device__ float g_ssum[N_ROWS];
__device__ float g_csum[K_CL];
__device__ float g_acw[K_CL];

// ---------------------------------------------------------------------------
// prep: row sum of squares for s  (one warp per row, 8 rows / 256-thread block)
// ---------------------------------------------------------------------------
__global__ void prep_s_kernel(const float* __restrict__ s) {
    int row  = blockIdx.x * (blockDim.x >> 5) + (threadIdx.x >> 5);
    int lane = threadIdx.x & 31;
    if (row >= N_ROWS) return;
    const float4* p = (const float4*)(s + (size_t)row * D_DIM);
    float acc = 0.f;
    #pragma unroll
    for (int i = lane; i < D_DIM / 4; i += 32) {
        float4 v = p[i];
        acc += v.x * v.x + v.y * v.y + v.z * v.z + v.w * v.w;
    }
    #pragma unroll
    for (int o = 16; o; o >>= 1) acc += __shfl_xor_sync(0xffffffffu, acc, o);
    if (lane == 0) g_ssum[row] = acc;
}

// prep: ||c||^2 and |c_weights|
__global__ void prep_c_kernel(const float* __restrict__ centers,
                              const float* __restrict__ cw) {
    int row  = blockIdx.x * (blockDim.x >> 5) + (threadIdx.x >> 5);
    int lane = threadIdx.x & 31;
    if (row >= K_CL) return;
    const float4* p = (const float4*)(centers + (size_t)row * D_DIM);
    float acc = 0.f;
    #pragma unroll
    for (int i = lane; i < D_DIM / 4; i += 32) {
        float4 v = p[i];
        acc += v.x * v.x + v.y * v.y + v.z * v.z + v.w * v.w;
    }
    #pragma unroll
    for (int o = 16; o; o >>= 1) acc += __shfl_xor_sync(0xffffffffu, acc, o);
    if (lane == 0) {
        g_csum[row] = acc;
        g_acw[row]  = fabsf(cw[row]);
    }
}

// ---------------------------------------------------------------------------
// fused main kernel: dist GEMM -> w -> (guarded) w @ means -> normalize
// 16x16 threads, each owns a 4x4 microtile of the 64x64 (row x k) dist tile
// and a 4x4 microtile of the 64x64 (row x A) mean accumulator.
// ---------------------------------------------------------------------------
__global__ __launch_bounds__(256) void fused_kernel(
    const float* __restrict__ s,
    const float* __restrict__ centers,
    const float* __restrict__ means,
    const float* __restrict__ log_temp,
    float* __restrict__ out)
{
    __shared__ float Ss[BD][BM];        // s tile, d-major
    __shared__ float Cs[BD][BK];        // centers tile, d-major
    __shared__ float Ws[BM][BK];        // w tile (only written when any w > 0)
    __shared__ float Ms[BK][A_DIM];     // means tile
    __shared__ float wred[BM];
    __shared__ int   anyflag;
    __shared__ float s_csum[BK];
    __shared__ float s_acw[BK];

    const int tx = threadIdx.x & 15;    // k / A microtile index
    const int ty = threadIdx.x >> 4;    // row microtile index
    const int rowbase = blockIdx.x * BM;

    const float tval = expf(log_temp[0]);

    float macc[4][4];
    float wrow[4];
    #pragma unroll
    for (int i = 0; i < 4; i++) {
        wrow[i] = 0.f;
        #pragma unroll
        for (int j = 0; j < 4; j++) macc[i][j] = 0.f;
    }

    float ssum_r[4];
    #pragma unroll
    for (int i = 0; i < 4; i++) ssum_r[i] = g_ssum[rowbase + ty * 4 + i];

    if (threadIdx.x < BM) wred[threadIdx.x] = 0.f;

    for (int kt = 0; kt < K_CL; kt += BK) {
        if (threadIdx.x < BK) {
            s_csum[threadIdx.x] = g_csum[kt + threadIdx.x];
            s_acw[threadIdx.x]  = g_acw[kt + threadIdx.x];
        }

        float dot[4][4];
        #pragma unroll
        for (int i = 0; i < 4; i++)
            #pragma unroll
            for (int j = 0; j < 4; j++) dot[i][j] = 0.f;

        for (int dt = 0; dt < D_DIM; dt += BD) {
            // cooperative transposed load: 64 rows x 16 d, one float4 per thread
            {
                int r = threadIdx.x >> 2;
                int q = threadIdx.x & 3;
                float4 v = *(const float4*)(s + (size_t)(rowbase + r) * D_DIM + dt + q * 4);
                Ss[q * 4 + 0][r] = v.x;
                Ss[q * 4 + 1][r] = v.y;
                Ss[q * 4 + 2][r] = v.z;
                Ss[q * 4 + 3][r] = v.w;
                float4 c = *(const float4*)(centers + (size_t)(kt + r) * D_DIM + dt + q * 4);
                Cs[q * 4 + 0][r] = c.x;
                Cs[q * 4 + 1][r] = c.y;
                Cs[q * 4 + 2][r] = c.z;
                Cs[q * 4 + 3][r] = c.w;
            }
            __syncthreads();
            #pragma unroll
            for (int d = 0; d < BD; d++) {
                float4 av = *(const float4*)(&Ss[d][ty * 4]);
                float4 bv = *(const float4*)(&Cs[d][tx * 4]);
                float a0 = av.x, a1 = av.y, a2 = av.z, a3 = av.w;
                float b0 = bv.x, b1 = bv.y, b2 = bv.z, b3 = bv.w;
                dot[0][0] += a0 * b0; dot[0][1] += a0 * b1; dot[0][2] += a0 * b2; dot[0][3] += a0 * b3;
                dot[1][0] += a1 * b0; dot[1][1] += a1 * b1; dot[1][2] += a1 * b2; dot[1][3] += a1 * b3;
                dot[2][0] += a2 * b0; dot[2][1] += a2 * b1; dot[2][2] += a2 * b2; dot[2][3] += a2 * b3;
                dot[3][0] += a3 * b0; dot[3][1] += a3 * b1; dot[3][2] += a3 * b2; dot[3][3] += a3 * b3;
            }
            __syncthreads();
        }

        // membership weights (exp guarded: expf returns 0 beyond -104 anyway)
        int local_any = 0;
        float wv[4][4];
        #pragma unroll
        for (int i = 0; i < 4; i++) {
            #pragma unroll
            for (int j = 0; j < 4; j++) {
                float dist = ssum_r[i] + s_csum[tx * 4 + j] - 2.0f * dot[i][j];
                float arg  = tval * dist;
                float w    = 0.f;
                if (arg < 104.0f) {
                    w = s_acw[tx * 4 + j] * expf(-arg);
                    if (w > 0.f) local_any = 1;
                }
                wv[i][j] = w;
                wrow[i] += w;
            }
        }

        if (threadIdx.x == 0) anyflag = 0;
        __syncthreads();
        if (local_any) anyflag = 1;
        __syncthreads();

        if (anyflag) {
            #pragma unroll
            for (int i = 0; i < 4; i++)
                #pragma unroll
                for (int j = 0; j < 4; j++)
                    Ws[ty * 4 + i][tx * 4 + j] = wv[i][j];
            // means tile is a contiguous 64x64 block of the row-major [K, A] array
            const float4* msrc = (const float4*)(means + (size_t)kt * A_DIM);
            #pragma unroll
            for (int t = threadIdx.x; t < BK * A_DIM / 4; t += 256)
                ((float4*)&Ms[0][0])[t] = msrc[t];
            __syncthreads();
            #pragma unroll 8
            for (int k = 0; k < BK; k++) {
                float4 m = *(const float4*)(&Ms[k][tx * 4]);
                #pragma unroll
                for (int i = 0; i < 4; i++) {
                    float w = Ws[ty * 4 + i][k];
                    macc[i][0] += w * m.x;
                    macc[i][1] += w * m.y;
                    macc[i][2] += w * m.z;
                    macc[i][3] += w * m.w;
                }
            }
            __syncthreads();
        }
    }

    // reduce per-row weight sums across the 16 tx threads sharing each row
    #pragma unroll
    for (int i = 0; i < 4; i++) atomicAdd(&wred[ty * 4 + i], wrow[i]);
    __syncthreads();

    #pragma unroll
    for (int i = 0; i < 4; i++) {
        float inv = 1.0f / (wred[ty * 4 + i] + 1.0f);
        float4 o;
        o.x = macc[i][0] * inv;
        o.y = macc[i][1] * inv;
        o.z = macc[i][2] * inv;
        o.w = macc[i][3] * inv;
        *(float4*)(out + (size_t)(rowbase + ty * 4 + i) * A_DIM + tx * 4) = o;
    }
}

// ---------------------------------------------------------------------------
// chol output: diag(exp(log_sigma)), written after the mean block
// ---------------------------------------------------------------------------
__global__ void chol_kernel(const float* __restrict__ log_sigma,
                            float* __restrict__ out2) {
    int idx = blockIdx.x * blockDim.x + threadIdx.x;
    if (idx < A_DIM * A_DIM) {
        int i = idx / A_DIM;
        int j = idx % A_DIM;
        out2[idx] = (i == j) ? expf(log_sigma[i]) : 0.f;
    }
}

extern "C" void kernel_launch(void* const* d_in, const int* in_sizes, int n_in,
                              void* d_out, int out_size) {
    const float* s        = (const float*)d_in[0];  // [N, D]
    const float* centers  = (const float*)d_in[1];  // [K, D]
    const float* cweights = (const float*)d_in[2];  // [K]
    const float* means    = (const float*)d_in[3];  // [K, A]
    const float* logsig   = (const float*)d_in[4];  // [A]
    const float* logtemp  = (const float*)d_in[5];  // [1]
    float* out = (float*)d_out;                     // [N*A + A*A]

    (void)in_sizes; (void)n_in; (void)out_size;

    prep_s_kernel<<<N_ROWS / 8, 256>>>(s);
    prep_c_kernel<<<K_CL / 8, 256>>>(centers, cweights);
    fused_kernel<<<N_ROWS / BM, 256>>>(s, centers, means, logtemp, out);
    chol_kernel<<<(A_DIM * A_DIM + 255) / 256, 256>>>(logsig, out + (size_t)N_ROWS * A_DIM);
}

// round 3
// speedup vs baseline: 5.9635x; 5.9635x over previous
#include <cuda_runtime.h>
#include <cuda_bf16.h>
#include <cstdint>
#include <math.h>

#define N_ROWS 65536
#define K_CL   1024
#define D_DIM  256
#define A_DIM  64

#define BM 128
#define BK 128
#define NTILES (K_CL / BK)   // 8

// ---- dynamic SMEM layout ----
#define SMEM_WSUM   64                    // float[128]
#define SMEM_S      2048                  // 65536 B: 4 chunks of 128r x 64c bf16 (SW128)
#define SMEM_C0     (SMEM_S + 65536)      // 67584
#define SMEM_C1     (SMEM_C0 + 65536)     // 133120
#define SMEM_MACC   (SMEM_C1 + 65536)     // 198656: float[128][64]
#define SMEM_TOTAL  (SMEM_MACC + 32768)   // 231424 <= 232448

// scratch device globals (allocation-free)
__device__ __nv_bfloat16 g_sbf[N_ROWS * D_DIM];
__device__ __nv_bfloat16 g_cbf[K_CL * D_DIM];
__device__ float g_ssum[N_ROWS];
__device__ float g_csum[K_CL];
__device__ float g_acw[K_CL];

// ---------------- helpers ----------------
__device__ __forceinline__ uint32_t smem_u32(const void* p) {
    uint32_t a;
    asm("{ .reg .u64 t; cvta.to.shared.u64 t, %1; cvt.u32.u64 %0, t; }"
        : "=r"(a) : "l"(p));
    return a;
}
#define SWZ(x) ((x) ^ (((x) >> 3) & 0x70))

__device__ __forceinline__ void ldsm_x4(uint32_t* r, uint32_t addr) {
    asm volatile("ldmatrix.sync.aligned.m8n8.x4.shared.b16 {%0,%1,%2,%3}, [%4];"
                 : "=r"(r[0]), "=r"(r[1]), "=r"(r[2]), "=r"(r[3]) : "r"(addr));
}
__device__ __forceinline__ void ldsm_x4_t(uint32_t* r, uint32_t addr) {
    asm volatile("ldmatrix.sync.aligned.m8n8.x4.trans.shared.b16 {%0,%1,%2,%3}, [%4];"
                 : "=r"(r[0]), "=r"(r[1]), "=r"(r[2]), "=r"(r[3]) : "r"(addr));
}
__device__ __forceinline__ void mma16816(float* d, const uint32_t* a, const uint32_t* b) {
    asm volatile(
        "mma.sync.aligned.m16n8k16.row.col.f32.bf16.bf16.f32 "
        "{%0,%1,%2,%3}, {%4,%5,%6,%7}, {%8,%9}, {%0,%1,%2,%3};"
        : "+f"(d[0]), "+f"(d[1]), "+f"(d[2]), "+f"(d[3])
        : "r"(a[0]), "r"(a[1]), "r"(a[2]), "r"(a[3]), "r"(b[0]), "r"(b[1]));
}

// ---------------- prep kernels: fp32 sums + bf16 conversion ----------------
__global__ void prep_s_kernel(const float* __restrict__ s) {
    int row  = blockIdx.x * 8 + (threadIdx.x >> 5);
    int lane = threadIdx.x & 31;
    const float4* p = (const float4*)(s + (size_t)row * D_DIM);
    float acc = 0.f;
    #pragma unroll
    for (int i = lane; i < D_DIM / 4; i += 32) {
        float4 v = p[i];
        acc += v.x * v.x + v.y * v.y + v.z * v.z + v.w * v.w;
        __nv_bfloat162 lo = __floats2bfloat162_rn(v.x, v.y);
        __nv_bfloat162 hi = __floats2bfloat162_rn(v.z, v.w);
        *(__nv_bfloat162*)(g_sbf + (size_t)row * D_DIM + i * 4)     = lo;
        *(__nv_bfloat162*)(g_sbf + (size_t)row * D_DIM + i * 4 + 2) = hi;
    }
    #pragma unroll
    for (int o = 16; o; o >>= 1) acc += __shfl_xor_sync(0xffffffffu, acc, o);
    if (lane == 0) g_ssum[row] = acc;
}

__global__ void prep_c_kernel(const float* __restrict__ centers,
                              const float* __restrict__ cw) {
    int row  = blockIdx.x * 8 + (threadIdx.x >> 5);
    int lane = threadIdx.x & 31;
    const float4* p = (const float4*)(centers + (size_t)row * D_DIM);
    float acc = 0.f;
    #pragma unroll
    for (int i = lane; i < D_DIM / 4; i += 32) {
        float4 v = p[i];
        acc += v.x * v.x + v.y * v.y + v.z * v.z + v.w * v.w;
        __nv_bfloat162 lo = __floats2bfloat162_rn(v.x, v.y);
        __nv_bfloat162 hi = __floats2bfloat162_rn(v.z, v.w);
        *(__nv_bfloat162*)(g_cbf + (size_t)row * D_DIM + i * 4)     = lo;
        *(__nv_bfloat162*)(g_cbf + (size_t)row * D_DIM + i * 4 + 2) = hi;
    }
    #pragma unroll
    for (int o = 16; o; o >>= 1) acc += __shfl_xor_sync(0xffffffffu, acc, o);
    if (lane == 0) {
        g_csum[row] = acc;
        g_acw[row]  = fabsf(cw[row]);
    }
}

// ---- tile loader: 128 rows x 256 bf16 -> 4 SW128 chunks (16KB each) ----
__device__ __forceinline__ void load_tile_bf16(uint32_t smem_dst,
                                               const __nv_bfloat16* gsrc) {
    int tid = threadIdx.x;
    #pragma unroll
    for (int i = 0; i < 16; i++) {
        int id  = tid + i * 256;          // 0..4095 16B segments
        int ch  = id >> 10;
        int row = (id >> 3) & 127;
        int seg = id & 7;
        const void* src = gsrc + (size_t)row * D_DIM + ch * 64 + seg * 8;
        uint32_t dst = smem_dst + ch * 16384 + SWZ(row * 128 + seg * 16);
        asm volatile("cp.async.cg.shared.global [%0], [%1], 16;" :: "r"(dst), "l"(src));
    }
    asm volatile("cp.async.commit_group;");
}

// ---- rare exact fallback (bf16 dist landed inside the exp-live window) ----
__device__ __noinline__ void exact_fallback(
    int grow, int kk, float tval,
    const float* __restrict__ s, const float* __restrict__ centers,
    const float* __restrict__ means, float* macc_sh, float* wsum_sh, int lrow)
{
    float de = 0.f;
    const float* sp = s + (size_t)grow * D_DIM;
    const float* cp = centers + (size_t)kk * D_DIM;
    for (int d = 0; d < D_DIM; d++) de += sp[d] * cp[d];
    float dist = g_ssum[grow] + g_csum[kk] - 2.0f * de;
    float w = g_acw[kk] * expf(-tval * dist);
    if (w > 0.f) {
        atomicAdd(&wsum_sh[lrow], w);
        const float* mp = means + (size_t)kk * A_DIM;
        for (int a = 0; a < A_DIM; a++)
            atomicAdd(&macc_sh[lrow * A_DIM + a], w * mp[a]);
    }
}

// ---------------- fused main kernel ----------------
__global__ void __launch_bounds__(256, 1) fused_kernel(
    const float* __restrict__ s,
    const float* __restrict__ centers,
    const float* __restrict__ means,
    const float* __restrict__ log_temp,
    float* __restrict__ out)
{
    extern __shared__ char smem[];
    const uint32_t sb = smem_u32(smem);
    const int tid  = threadIdx.x;
    const int wid  = tid >> 5;
    const int lane = tid & 31;
    const int wm   = wid & 3;      // warp row block (32 rows)
    const int wn   = wid >> 2;     // warp col block (64 cols)
    const int rowbase = blockIdx.x * BM;

    const float tval = expf(log_temp[0]);
    const float trigger = 104.0f + fmaxf(8.0f * tval, 8.0f);

    float* wsum_sh = (float*)(smem + SMEM_WSUM);
    float* macc_sh = (float*)(smem + SMEM_MACC);

    if (tid < 128) wsum_sh[tid] = 0.f;
    #pragma unroll
    for (int i = 0; i < 8; i++)
        ((float4*)macc_sh)[tid + i * 256] = make_float4(0.f, 0.f, 0.f, 0.f);

    // prologue: s tile + first two c tiles in flight
    load_tile_bf16(sb + SMEM_S,  g_sbf + (size_t)rowbase * D_DIM);   // group A
    load_tile_bf16(sb + SMEM_C0, g_cbf);                              // group B
    load_tile_bf16(sb + SMEM_C1, g_cbf + (size_t)BK * D_DIM);        // group C

    // per-lane ldmatrix addressing (swizzle folds to a per-lane XOR constant)
    const uint32_t xorv   = (uint32_t)((lane & 7) << 4);
    const uint32_t sA     = sb + SMEM_S + (uint32_t)((wm * 32 + (lane & 15)) * 128);
    const uint32_t rowoffB = (uint32_t)((wn * 64 + (lane & 7) + ((lane >> 4) & 1) * 8) * 128);

    // epilogue row constants
    const int r0m[2] = { wm * 32 + (lane >> 2), wm * 32 + 16 + (lane >> 2) };
    float ssA[2], ssB[2];
    #pragma unroll
    for (int mt = 0; mt < 2; mt++) {
        ssA[mt] = g_ssum[rowbase + r0m[mt]];
        ssB[mt] = g_ssum[rowbase + r0m[mt] + 8];
    }

    for (int t = 0; t < NTILES; t++) {
        // wait until tile t resident (allow one later tile in flight)
        if (t < NTILES - 2) asm volatile("cp.async.wait_group 1;" ::: "memory");
        else                asm volatile("cp.async.wait_group 0;" ::: "memory");
        __syncthreads();

        const uint32_t cbuf = sb + ((t & 1) ? SMEM_C1 : SMEM_C0) + rowoffB;

        float acc[2][8][4];
        #pragma unroll
        for (int mt = 0; mt < 2; mt++)
            #pragma unroll
            for (int nt = 0; nt < 8; nt++)
                #pragma unroll
                for (int v = 0; v < 4; v++) acc[mt][nt][v] = 0.f;

        #pragma unroll
        for (int ks = 0; ks < 16; ks++) {
            const uint32_t choff = (uint32_t)(ks >> 2) * 16384u;
            uint32_t a[2][4], b[4][4];
            const uint32_t csA = (uint32_t)((((ks & 3) * 2 + (lane >> 4)) * 16)) ^ xorv;
            ldsm_x4(a[0], sA + choff + csA);
            ldsm_x4(a[1], sA + choff + 2048u + csA);
            const uint32_t csB = (uint32_t)((((ks & 3) * 2 + ((lane >> 3) & 1)) * 16)) ^ xorv;
            #pragma unroll
            for (int p = 0; p < 4; p++)
                ldsm_x4_t(b[p], cbuf + choff + (uint32_t)p * 2048u + csB);
            #pragma unroll
            for (int mt = 0; mt < 2; mt++)
                #pragma unroll
                for (int nt = 0; nt < 8; nt++)
                    mma16816(acc[mt][nt], a[mt], &b[nt >> 1][(nt & 1) * 2]);
        }

        __syncthreads();
        // prefetch tile t+2 into the buffer tile t just freed
        if (t + 2 < NTILES)
            load_tile_bf16(sb + ((t & 1) ? SMEM_C1 : SMEM_C0),
                           g_cbf + (size_t)(t + 2) * BK * D_DIM);

        // epilogue: dist + exp-cutoff test (rare exact fallback)
        #pragma unroll
        for (int mt = 0; mt < 2; mt++) {
            #pragma unroll
            for (int nt = 0; nt < 8; nt++) {
                const int kk = t * BK + wn * 64 + nt * 8 + (lane & 3) * 2;
                const float2 cs = __ldg((const float2*)&g_csum[kk]);
                float d0 = ssA[mt] + cs.x - 2.0f * acc[mt][nt][0];
                float d1 = ssA[mt] + cs.y - 2.0f * acc[mt][nt][1];
                float d2 = ssB[mt] + cs.x - 2.0f * acc[mt][nt][2];
                float d3 = ssB[mt] + cs.y - 2.0f * acc[mt][nt][3];
                if (tval * d0 < trigger)
                    exact_fallback(rowbase + r0m[mt], kk, tval, s, centers, means,
                                   macc_sh, wsum_sh, r0m[mt]);
                if (tval * d1 < trigger)
                    exact_fallback(rowbase + r0m[mt], kk + 1, tval, s, centers, means,
                                   macc_sh, wsum_sh, r0m[mt]);
                if (tval * d2 < trigger)
                    exact_fallback(rowbase + r0m[mt] + 8, kk, tval, s, centers, means,
                                   macc_sh, wsum_sh, r0m[mt] + 8);
                if (tval * d3 < trigger)
                    exact_fallback(rowbase + r0m[mt] + 8, kk + 1, tval, s, centers, means,
                                   macc_sh, wsum_sh, r0m[mt] + 8);
            }
        }
    }

    __syncthreads();

    // normalized mean write: thread handles row tid>>1, col half 32*(tid&1)
    const int orow  = tid >> 1;
    const int ocol  = (tid & 1) * 32;
    const float inv = 1.0f / (wsum_sh[orow] + 1.0f);
    #pragma unroll
    for (int i = 0; i < 8; i++) {
        float4 m = *(float4*)&macc_sh[orow * A_DIM + ocol + i * 4];
        float4 o = make_float4(m.x * inv, m.y * inv, m.z * inv, m.w * inv);
        *(float4*)(out + (size_t)(rowbase + orow) * A_DIM + ocol + i * 4) = o;
    }
}

// ---------------- chol: diag(exp(log_sigma)) ----------------
__global__ void chol_kernel(const float* __restrict__ log_sigma,
                            float* __restrict__ out2) {
    int idx = blockIdx.x * blockDim.x + threadIdx.x;
    if (idx < A_DIM * A_DIM) {
        int i = idx / A_DIM, j = idx % A_DIM;
        out2[idx] = (i == j) ? expf(log_sigma[i]) : 0.f;
    }
}

extern "C" void kernel_launch(void* const* d_in, const int* in_sizes, int n_in,
                              void* d_out, int out_size) {
    const float* s       = (const float*)d_in[0];
    const float* centers = (const float*)d_in[1];
    const float* cw      = (const float*)d_in[2];
    const float* means   = (const float*)d_in[3];
    const float* logsig  = (const float*)d_in[4];
    const float* logtemp = (const float*)d_in[5];
    float* out = (float*)d_out;
    (void)in_sizes; (void)n_in; (void)out_size;

    cudaFuncSetAttribute(fused_kernel,
                         cudaFuncAttributeMaxDynamicSharedMemorySize, SMEM_TOTAL);

    prep_s_kernel<<<N_ROWS / 8, 256>>>(s);
    prep_c_kernel<<<K_CL / 8, 256>>>(centers, cw);
    fused_kernel<<<N_ROWS / BM, 256, SMEM_TOTAL>>>(s, centers, means, logtemp, out);
    chol_kernel<<<(A_DIM * A_DIM + 255) / 256, 256>>>(logsig, out + (size_t)N_ROWS * A_DIM);
}